// round 17
// baseline (speedup 1.0000x reference)
#include <cuda_runtime.h>
#include <cuda_bf16.h>
#include <cstdint>

// ---------------- problem dims ----------------
#define BDIM  64
#define SDIM  2048
#define EDIM  1024
#define DDIM  1024
#define SYNCD 512
#define MDIM  32
#define NHEADS 16
#define DH    64
#define SYNH  2048
#define TRH   64

typedef unsigned int uint32;

// ---------------- scratch (static device globals; no allocation) ----------------
__device__ __nv_bfloat16 g_kv [(size_t)BDIM * SDIM * EDIM];   // x_context + zH, bf16 (written by gemm_kw)
__device__ __nv_bfloat16 g_wkT[(size_t)EDIM * EDIM];          // wk transposed: [n][k]
__device__ float g_wpart[2][(size_t)BDIM * NHEADS * SDIM];    // per-half-head w partials
__device__ __nv_bfloat16 g_wbf[(size_t)BDIM * NHEADS * SDIM]; // w[b,h,s] bf16 (for ugemm)
__device__ float g_den [BDIM * NHEADS];                       // sum_s w (fp32 exact)
__device__ float g_u   [(size_t)BDIM * NHEADS * EDIM];        // u[b,h,:] = sum_s w*kv[b,s,:]
__device__ float g_q    [BDIM * EDIM];
__device__ float g_pq   [BDIM * EDIM];
__device__ float g_attn [BDIM * EDIM];
__device__ float g_pre  [BDIM * 2048];                        // [attn_out | activated_zL]
__device__ float g_hidden[BDIM * SYNH];
__device__ float g_state[BDIM * DDIM];
__device__ float g_partial[(size_t)16 * 64 * 2048];           // split-K partials

// ---------------- helpers ----------------
__device__ __forceinline__ float phi_f(float x) { return x > 0.f ? x + 1.f : __expf(x); }

__device__ __forceinline__ uint32 smem_u32(const void* p) {
    return (uint32)__cvta_generic_to_shared(p);
}

#define CP_ASYNC16(dst, src) \
    asm volatile("cp.async.cg.shared.global [%0], [%1], 16;" :: "r"(dst), "l"(src) : "memory")
#define CP_COMMIT() asm volatile("cp.async.commit_group;" ::: "memory")
#define CP_WAIT(n)  asm volatile("cp.async.wait_group %0;" :: "n"(n) : "memory")

#define LDSM4(r0, r1, r2, r3, addr) \
    asm volatile("ldmatrix.sync.aligned.m8n8.x4.shared.b16 {%0,%1,%2,%3}, [%4];" \
                 : "=r"(r0), "=r"(r1), "=r"(r2), "=r"(r3) : "r"(addr))

__device__ __forceinline__ void mma16816(float* d, const uint32* a, const uint32* b) {
    asm volatile(
        "mma.sync.aligned.m16n8k16.row.col.f32.bf16.bf16.f32 "
        "{%0,%1,%2,%3},{%4,%5,%6,%7},{%8,%9},{%0,%1,%2,%3};\n"
        : "+f"(d[0]), "+f"(d[1]), "+f"(d[2]), "+f"(d[3])
        : "r"(a[0]), "r"(a[1]), "r"(a[2]), "r"(a[3]), "r"(b[0]), "r"(b[1]));
}

// ---------------- pack: transpose wk -> g_wkT[n][k] bf16 ----------------
__global__ void __launch_bounds__(256) pack_wT_kernel(const float* __restrict__ wk) {
    __shared__ float tile[32][33];
    int tx = threadIdx.x & 31, ty = threadIdx.x >> 5;  // 32 x 8
    int n0 = blockIdx.x * 32;
    int k0 = blockIdx.y * 32;
#pragma unroll
    for (int j = 0; j < 32; j += 8) {
        int k = k0 + ty + j;
        tile[ty + j][tx] = wk[(size_t)k * 1024 + n0 + tx];
    }
    __syncthreads();
#pragma unroll
    for (int j = 0; j < 32; j += 8) {
        int n = n0 + ty + j;
        int k = k0 + tx;
        g_wkT[(size_t)n * 1024 + k] = __float2bfloat16(tile[tx][ty + j]);
    }
}

// ---------------- split-K small GEMM: partial[split] = A[64][Kc-slice] @ W ----------------
__global__ void __launch_bounds__(256) gemm_splitk_kernel(
    const float* __restrict__ A, int K, int Kc,
    const float* __restrict__ W, float* __restrict__ partial, int N) {
    __shared__ float sA[64][33];
    __shared__ float sW[32][65];
    int tid = threadIdx.x;
    int g = tid >> 6, nn = tid & 63;
    int n0 = blockIdx.x * 64;
    int k0 = blockIdx.y * Kc;
    float acc[16];
#pragma unroll
    for (int i = 0; i < 16; i++) acc[i] = 0.f;

    for (int kc = k0; kc < k0 + Kc; kc += 32) {
        for (int idx = tid; idx < 2048; idx += 256) {
            int bb = idx >> 5, kk = idx & 31;
            sA[bb][kk] = A[(size_t)bb * K + kc + kk];
        }
        for (int idx = tid; idx < 2048; idx += 256) {
            int kk = idx >> 6, n_ = idx & 63;
            sW[kk][n_] = W[(size_t)(kc + kk) * N + n0 + n_];
        }
        __syncthreads();
#pragma unroll 8
        for (int kk = 0; kk < 32; kk++) {
            float w = sW[kk][nn];
#pragma unroll
            for (int bl = 0; bl < 16; bl++)
                acc[bl] += sA[g * 16 + bl][kk] * w;
        }
        __syncthreads();
    }
    float* out = partial + (size_t)blockIdx.y * 64 * N;
#pragma unroll
    for (int bl = 0; bl < 16; bl++)
        out[(size_t)(g * 16 + bl) * N + n0 + nn] = acc[bl];
}

// act: 0 none, 1 relu, 2 phi
__global__ void reduce_act_kernel(const float* __restrict__ partial, int nsplit,
                                  const float* __restrict__ bias,
                                  float* __restrict__ out, int N, int out_stride, int act) {
    int i = blockIdx.x * blockDim.x + threadIdx.x;
    if (i >= 64 * N) return;
    int b = i / N, n = i - b * N;
    float acc = bias ? bias[n] : 0.f;
    for (int s = 0; s < nsplit; s++) acc += partial[(size_t)s * 64 * N + i];
    if (act == 1) acc = fmaxf(acc, 0.f);
    else if (act == 2) acc = phi_f(acc);
    out[(size_t)b * out_stride + n] = acc;
}

// ---------------- K GEMM + fused convert + fused wdot ------------------------------------
// A = bf16(x + zH) computed in-kernel from fp32 x (staging smem); bx==0 CTAs write g_kv.
// CTA tile 128(M) x 256(N), k-chunks of 32, 4-stage cp.async (staging fp32 A + bf16 B).
// sA (bf16, ldmatrix source) is single-buffered: convert->consume within one iteration.
// Epilogue: w-partials = per-half-head dot of phi(y+bk) with pq.
#define KW_STG_STRIDE 144
#define KW_STAGING_BYTES (128 * KW_STG_STRIDE)        // 18432 per stage
#define KW_SB_BYTES (256 * 80)                        // 20480 per stage
#define KW_SA_BYTES (128 * 80)                        // 10240 single buffer
#define KW_STAGING_OFF 0
#define KW_SB_OFF (4 * KW_STAGING_BYTES)              // 73728
#define KW_SA_OFF (KW_SB_OFF + 4 * KW_SB_BYTES)       // 155648
#define KW_ZH_OFF (KW_SA_OFF + KW_SA_BYTES)           // 165888
#define KW_SMEM_BYTES (KW_ZH_OFF + 4096)              // 169984

__global__ void __launch_bounds__(512, 1) gemm_kw_kernel(const float* __restrict__ x,
                                                         const float* __restrict__ zH,
                                                         const float* __restrict__ bk) {
    extern __shared__ char sm_raw[];
    uint32 base = smem_u32(sm_raw);
    int tid = threadIdx.x, warp = tid >> 5, lane = tid & 31;
    int gid = lane >> 2, tig = lane & 3;
    int wm = warp >> 3, wn = warp & 7;             // 2 x 8 warp grid, warp tile 64x32
    int n0 = blockIdx.x * 256, m0 = blockIdx.y * 128;
    int b = m0 >> 11;

    const float*         srcA  = x     + (size_t)m0 * 1024;
    const __nv_bfloat16* baseB = g_wkT + (size_t)n0 * 1024;
    float* zhp = (float*)(sm_raw + KW_ZH_OFF);

    // preload zH row for this batch
    for (int i = tid; i < 1024; i += 512) zhp[i] = zH[b * 1024 + i];

    float acc[4][4][4];
#pragma unroll
    for (int mi = 0; mi < 4; mi++)
#pragma unroll
        for (int ni = 0; ni < 4; ni++)
#pragma unroll
            for (int q = 0; q < 4; q++) acc[mi][ni][q] = 0.f;

    auto load_chunk = [&](int c, int s) {
        uint32 stg = base + KW_STAGING_OFF + s * KW_STAGING_BYTES;
        uint32 sb  = base + KW_SB_OFF + s * KW_SB_BYTES;
        int kc = c * 32;
#pragma unroll
        for (int t = 0; t < 2; t++) {              // A fp32: 1024 x 16B
            int i = tid + t * 512;
            int row = i >> 3, seg = i & 7;
            CP_ASYNC16(stg + row * KW_STG_STRIDE + seg * 16,
                       srcA + (size_t)row * 1024 + kc + seg * 4);
        }
#pragma unroll
        for (int t = 0; t < 2; t++) {              // B bf16: 1024 x 16B
            int i = tid + t * 512;
            int row = i >> 2, seg = i & 3;
            CP_ASYNC16(sb + row * 80 + seg * 16,
                       baseB + (size_t)row * 1024 + kc + seg * 8);
        }
    };

    load_chunk(0, 0); CP_COMMIT();
    load_chunk(1, 1); CP_COMMIT();
    load_chunk(2, 2); CP_COMMIT();

    // per-lane ldmatrix offsets
    uint32 saddrA = base + KW_SA_OFF + ((wm * 64 + (lane & 15)) * 80 + (lane >> 4) * 16);
    int rowB_off = (wn * 32 + (lane & 7) + ((lane >> 4) << 3)) * 80 + ((lane >> 3) & 1) * 16;

    // convert indices: thread -> (row, 8-col segment)
    int cvt_row = tid >> 2, cvt_cb = (tid & 3) * 8;
    __nv_bfloat16* sap = (__nv_bfloat16*)(sm_raw + KW_SA_OFF);
    bool writeback = (blockIdx.x == 0);

    for (int c = 0; c < 32; c++) {
        if (c <= 29)      { CP_WAIT(2); }
        else if (c == 30) { CP_WAIT(1); }
        else              { CP_WAIT(0); }
        __syncthreads();   // staging/sB ready; prior sA reads complete

        // convert staging fp32 -> sA bf16 (+zH), optional writeback to g_kv
        {
            int s = c & 3;
            int kc = c * 32;
            const float* stgp = (const float*)(sm_raw + KW_STAGING_OFF + s * KW_STAGING_BYTES)
                                + cvt_row * 36 + cvt_cb;
            float4 a0 = *(const float4*)stgp;
            float4 a1 = *(const float4*)(stgp + 4);
            const float* zp = zhp + kc + cvt_cb;
            union { uint32 u[4]; uint4 v; } pk;
            __nv_bfloat162 t0, t1, t2, t3;
            t0.x = __float2bfloat16(a0.x + zp[0]); t0.y = __float2bfloat16(a0.y + zp[1]);
            t1.x = __float2bfloat16(a0.z + zp[2]); t1.y = __float2bfloat16(a0.w + zp[3]);
            t2.x = __float2bfloat16(a1.x + zp[4]); t2.y = __float2bfloat16(a1.y + zp[5]);
            t3.x = __float2bfloat16(a1.z + zp[6]); t3.y = __float2bfloat16(a1.w + zp[7]);
            pk.u[0] = *(uint32*)&t0; pk.u[1] = *(uint32*)&t1;
            pk.u[2] = *(uint32*)&t2; pk.u[3] = *(uint32*)&t3;
            *(uint4*)(sap + cvt_row * 40 + cvt_cb) = pk.v;
            if (writeback)
                *(uint4*)(g_kv + (size_t)(m0 + cvt_row) * 1024 + kc + cvt_cb) = pk.v;
        }

        if (c + 3 < 32) { load_chunk(c + 3, (c + 3) & 3); CP_COMMIT(); }
        __syncthreads();   // sA ready

        uint32 sb = base + KW_SB_OFF + (c & 3) * KW_SB_BYTES;
#pragma unroll
        for (int ks = 0; ks < 2; ks++) {
            uint32 afr[4][4], bfr[4][2];
#pragma unroll
            for (int mi = 0; mi < 4; mi++)
                LDSM4(afr[mi][0], afr[mi][1], afr[mi][2], afr[mi][3],
                      saddrA + mi * 16 * 80 + ks * 32);
#pragma unroll
            for (int nj = 0; nj < 2; nj++)
                LDSM4(bfr[2 * nj][0], bfr[2 * nj][1], bfr[2 * nj + 1][0], bfr[2 * nj + 1][1],
                      sb + rowB_off + nj * 16 * 80 + ks * 32);
#pragma unroll
            for (int mi = 0; mi < 4; mi++)
#pragma unroll
                for (int ni = 0; ni < 4; ni++)
                    mma16816(acc[mi][ni], afr[mi], bfr[ni]);
        }
    }

    // fused epilogue: w-partials = sum_{cols of this warp's half-head} phi(y+bk)*pq
    int s_base = m0 & 2047;
    int hh = (n0 >> 6) + (wn >> 1);
    int half = wn & 1;

    float pqv[8], bkv[8];
#pragma unroll
    for (int ni = 0; ni < 4; ni++) {
        int ng = n0 + wn * 32 + ni * 8 + tig * 2;
        pqv[2 * ni]     = g_pq[b * 1024 + ng];
        pqv[2 * ni + 1] = g_pq[b * 1024 + ng + 1];
        bkv[2 * ni]     = bk[ng];
        bkv[2 * ni + 1] = bk[ng + 1];
    }
    float* wp = g_wpart[half] + (size_t)(b * 16 + hh) * 2048;
#pragma unroll
    for (int mi = 0; mi < 4; mi++) {
        float p0 = 0.f, p1 = 0.f;
#pragma unroll
        for (int ni = 0; ni < 4; ni++) {
            p0 += phi_f(acc[mi][ni][0] + bkv[2 * ni]) * pqv[2 * ni]
                + phi_f(acc[mi][ni][1] + bkv[2 * ni + 1]) * pqv[2 * ni + 1];
            p1 += phi_f(acc[mi][ni][2] + bkv[2 * ni]) * pqv[2 * ni]
                + phi_f(acc[mi][ni][3] + bkv[2 * ni + 1]) * pqv[2 * ni + 1];
        }
        p0 += __shfl_xor_sync(0xFFFFFFFFu, p0, 1);
        p0 += __shfl_xor_sync(0xFFFFFFFFu, p0, 2);
        p1 += __shfl_xor_sync(0xFFFFFFFFu, p1, 1);
        p1 += __shfl_xor_sync(0xFFFFFFFFu, p1, 2);
        if (tig == 0) {
            int s0 = s_base + wm * 64 + mi * 16 + gid;
            wp[s0]     = p0;
            wp[s0 + 8] = p1;
        }
    }
}

// ---------------- wden: w = part0 + part1 (-> bf16) ; den = sum_s w (fp32) ----------------
__global__ void __launch_bounds__(256) wden_kernel() {
    __shared__ float sred[256];
    int bh = blockIdx.x, tid = threadIdx.x;
    size_t base = (size_t)bh * 2048;
    float dsum = 0.f;
#pragma unroll
    for (int i = 0; i < 8; i++) {
        int s = tid + i * 256;
        float wv = g_wpart[0][base + s] + g_wpart[1][base + s];
        g_wbf[base + s] = __float2bfloat16(wv);
        dsum += wv;
    }
    sred[tid] = dsum;
    __syncthreads();
#pragma unroll
    for (int off = 128; off >= 1; off >>= 1) {
        if (tid < off) sred[tid] += sred[tid + off];
        __syncthreads();
    }
    if (tid == 0) g_den[bh] = sred[0];
}

// ---------------- ugemm (mma): u[b][16][1024] = w_bf[b][16][2048] @ kv[b][2048][1024] --------
__global__ void __launch_bounds__(128) ugemm_kernel() {
    __shared__ __nv_bfloat16 sA[16][74];
    __shared__ __nv_bfloat16 sB[128][74];
    int tid = threadIdx.x, warp = tid >> 5, lane = tid & 31;
    int gid = lane >> 2, tig = lane & 3;
    int n0 = blockIdx.x * 128, b = blockIdx.y;
    const __nv_bfloat16* A  = g_wbf + (size_t)b * 16 * 2048;
    const __nv_bfloat16* KV = g_kv  + (size_t)b * 2048 * 1024;

    float acc[4][4];
#pragma unroll
    for (int ni = 0; ni < 4; ni++)
#pragma unroll
        for (int q = 0; q < 4; q++) acc[ni][q] = 0.f;

    for (int sc = 0; sc < 2048; sc += 64) {
#pragma unroll
        for (int t = 0; t < 4; t++) {
            int idx = tid + t * 128;
            int h = idx >> 5, sl = (idx & 31) * 2;
            *(uint32*)&sA[h][sl] = *(const uint32*)&A[(size_t)h * 2048 + sc + sl];
        }
#pragma unroll
        for (int t = 0; t < 32; t++) {
            int idx = tid + t * 128;
            int s_l = idx >> 6, ep = idx & 63;
            uint32 v = *(const uint32*)&KV[(size_t)(sc + s_l) * 1024 + n0 + ep * 2];
            __nv_bfloat162 p = *(__nv_bfloat162*)&v;
            sB[ep * 2][s_l]     = p.x;
            sB[ep * 2 + 1][s_l] = p.y;
        }
        __syncthreads();
#pragma unroll
        for (int ks = 0; ks < 4; ks++) {
            int k = ks * 16;
            uint32 afr[4], bfr[4][2];
            afr[0] = *(uint32*)&sA[gid][k + tig * 2];
            afr[1] = *(uint32*)&sA[gid + 8][k + tig * 2];
            afr[2] = *(uint32*)&sA[gid][k + tig * 2 + 8];
            afr[3] = *(uint32*)&sA[gid + 8][k + tig * 2 + 8];
#pragma unroll
            for (int ni = 0; ni < 4; ni++) {
                int n = warp * 32 + ni * 8 + gid;
                bfr[ni][0] = *(uint32*)&sB[n][k + tig * 2];
                bfr[ni][1] = *(uint32*)&sB[n][k + tig * 2 + 8];
            }
#pragma unroll
            for (int ni = 0; ni < 4; ni++) mma16816(acc[ni], afr, bfr[ni]);
        }
        __syncthreads();
    }

    float* ub = g_u + (size_t)b * 16 * 1024;
#pragma unroll
    for (int ni = 0; ni < 4; ni++) {
        int c = n0 + warp * 32 + ni * 8 + tig * 2;
        ub[gid * 1024 + c]           = acc[ni][0];
        ub[gid * 1024 + c + 1]       = acc[ni][1];
        ub[(gid + 8) * 1024 + c]     = acc[ni][2];
        ub[(gid + 8) * 1024 + c + 1] = acc[ni][3];
    }
}

// ---------------- numk: attn = (u.wv_h + den*bv)/(den+eps); copy zL -> pre ----------------
__global__ void __launch_bounds__(256) numk_kernel(const float* __restrict__ wv,
                                                   const float* __restrict__ bv,
                                                   const float* __restrict__ zL) {
    __shared__ float su[1024];
    __shared__ float sred[4][64];
    int bh = blockIdx.x;
    int b = bh >> 4, h = bh & 15;
    int tid = threadIdx.x;
    for (int i = tid; i < 1024; i += 256) su[i] = g_u[(size_t)bh * 1024 + i];
    __syncthreads();
    int grp = tid >> 6, c = tid & 63;
    int col = h * 64 + c;
    const float* wcol = wv + col;
    float part = 0.f;
#pragma unroll 4
    for (int e = grp * 256; e < grp * 256 + 256; e++)
        part += su[e] * wcol[(size_t)e * 1024];
    sred[grp][c] = part;
    __syncthreads();
    if (tid < 64) {
        float den = g_den[bh];
        float num = sred[0][tid] + sred[1][tid] + sred[2][tid] + sred[3][tid]
                  + den * bv[h * 64 + tid];
        float attn = num / (den + 1e-6f);
        g_attn[b * 1024 + h * 64 + tid] = attn;
        g_pre[(size_t)b * 2048 + 1024 + h * 64 + tid] = zL[b * 1024 + h * 64 + tid];
    }
}

// ---------------- trace shift + trace processor -> both outputs ----------------
__global__ void __launch_bounds__(256) trace_kernel(const float* __restrict__ zt,
                                                    const float* __restrict__ w1,
                                                    const float* __restrict__ b1,
                                                    const float* __restrict__ w2,
                                                    const float* __restrict__ b2p,
                                                    float* __restrict__ out) {
    __shared__ float sT[64][33];
    __shared__ float sW1[32][64];
    __shared__ float sB1[64];
    __shared__ float sW2[64];
    __shared__ float sRed[4][64];
    int tid = threadIdx.x;
    int r0 = blockIdx.x * 64;
    float* out_act = out;
    float* out_tr = out + BDIM * DDIM;

    for (int idx = tid; idx < 2048; idx += 256) {
        int rr = idx >> 5, mm = idx & 31;
        float v = (mm < 31) ? zt[(size_t)(r0 + rr) * 32 + mm + 1] : g_state[r0 + rr];
        sT[rr][mm] = v;
        out_tr[(size_t)(r0 + rr) * 32 + mm] = v;
    }
    for (int idx = tid; idx < 2048; idx += 256) {
        int m = idx >> 6, hh = idx & 63;
        sW1[m][hh] = w1[idx];
    }
    if (tid < 64) { sB1[tid] = b1[tid]; sW2[tid] = w2[tid]; }
    __syncthreads();

    int rr = tid & 63, part = tid >> 6;
    float acc = 0.f;
#pragma unroll
    for (int hi = 0; hi < 16; hi++) {
        int hh = part * 16 + hi;
        float hs = sB1[hh];
#pragma unroll
        for (int m = 0; m < 32; m++) hs += sT[rr][m] * sW1[m][hh];
        acc += fmaxf(hs, 0.f) * sW2[hh];
    }
    sRed[part][rr] = acc;
    __syncthreads();
    if (tid < 64)
        out_act[r0 + tid] = sRed[0][tid] + sRed[1][tid] + sRed[2][tid] + sRed[3][tid] + b2p[0];
}

// ---------------- launch ----------------
extern "C" void kernel_launch(void* const* d_in, const int* in_sizes, int n_in,
                              void* d_out, int out_size) {
    (void)in_sizes; (void)n_in; (void)out_size;
    const float* zL  = (const float*)d_in[0];
    const float* zt  = (const float*)d_in[1];
    const float* zH  = (const float*)d_in[2];
    const float* x   = (const float*)d_in[3];
    const float* sy  = (const float*)d_in[4];
    const float* qpw = (const float*)d_in[5];
    const float* qpb = (const float*)d_in[6];
    const float* wq  = (const float*)d_in[7];
    const float* bq  = (const float*)d_in[8];
    const float* wk  = (const float*)d_in[9];
    const float* bk  = (const float*)d_in[10];
    const float* wv  = (const float*)d_in[11];
    const float* bv  = (const float*)d_in[12];
    const float* wo  = (const float*)d_in[13];
    const float* bo  = (const float*)d_in[14];
    const float* sw1 = (const float*)d_in[15];
    const float* sb1 = (const float*)d_in[16];
    const float* sw2 = (const float*)d_in[17];
    const float* sb2 = (const float*)d_in[18];
    const float* tw1 = (const float*)d_in[19];
    const float* tb1 = (const float*)d_in[20];
    const float* tw2 = (const float*)d_in[21];
    const float* tb2 = (const float*)d_in[22];
    float* out = (float*)d_out;

    float *p_q, *p_pq, *p_pre, *p_hidden, *p_state, *p_attn, *p_partial;
    cudaGetSymbolAddress((void**)&p_q,       g_q);
    cudaGetSymbolAddress((void**)&p_pq,      g_pq);
    cudaGetSymbolAddress((void**)&p_pre,     g_pre);
    cudaGetSymbolAddress((void**)&p_hidden,  g_hidden);
    cudaGetSymbolAddress((void**)&p_state,   g_state);
    cudaGetSymbolAddress((void**)&p_attn,    g_attn);
    cudaGetSymbolAddress((void**)&p_partial, g_partial);

    cudaFuncSetAttribute(gemm_kw_kernel,
                         cudaFuncAttributeMaxDynamicSharedMemorySize, KW_SMEM_BYTES);

    // weight prep
    pack_wT_kernel<<<dim3(32, 32), 256>>>(wk);

    // q path (split-K, widened): q = sy@qp_w + qp_b ; pq = phi(q@wq + bq)
    gemm_splitk_kernel<<<dim3(16, 8), 256>>>(sy, SYNCD, 64, qpw, p_partial, 1024);
    reduce_act_kernel<<<256, 256>>>(p_partial, 8, qpb, p_q, 1024, 1024, 0);
    gemm_splitk_kernel<<<dim3(16, 16), 256>>>(p_q, 1024, 64, wq, p_partial, 1024);
    reduce_act_kernel<<<256, 256>>>(p_partial, 16, bq, p_pq, 1024, 1024, 2);

    // K projection GEMM with fused convert (x+zH->bf16, writes g_kv) + fused wdot epilogue
    gemm_kw_kernel<<<dim3(4, 1024), 512, KW_SMEM_BYTES>>>(x, zH, bk);

    // w(bf16) + den(fp32)
    wden_kernel<<<1024, 256>>>();

    // u = w @ kv on tensor cores (fp32 accum, full K per CTA)
    ugemm_kernel<<<dim3(8, 64), 128>>>();

    // attn = (u@wv_h + den*bv)/(den+eps); copy zL -> pre[:,1024:]
    numk_kernel<<<1024, 256>>>(wv, bv, zL);

    // attn_out = attn @ wo + bo -> pre[:,0:1024]
    gemm_splitk_kernel<<<dim3(16, 16), 256>>>(p_attn, 1024, 64, wo, p_partial, 1024);
    reduce_act_kernel<<<256, 256>>>(p_partial, 16, bo, p_pre, 1024, 2048, 0);

    // synapse MLP
    gemm_splitk_kernel<<<dim3(32, 16), 256>>>(p_pre, 2048, 128, sw1, p_partial, 2048);
    reduce_act_kernel<<<512, 256>>>(p_partial, 16, sb1, p_hidden, 2048, 2048, 1);
    gemm_splitk_kernel<<<dim3(16, 16), 256>>>(p_hidden, 2048, 128, sw2, p_partial, 1024);
    reduce_act_kernel<<<256, 256>>>(p_partial, 16, sb2, p_state, 1024, 1024, 0);

    // trace update + processor -> writes both outputs
    trace_kernel<<<1024, 256>>>(zt, tw1, tb1, tw2, tb2, out);
}